// round 4
// baseline (speedup 1.0000x reference)
#include <cuda_runtime.h>
#include <cuda_fp16.h>
#include <cstdint>
#include <cstddef>

#define BB    8192
#define DIN   1024
#define CCAP  12
#define DOUT  1024
#define NTOT  (CCAP*DOUT)     // 12288
#define AREP  8

// ---------------- device scratch (static; no allocation) ----------------
__device__ __half g_xh[(size_t)BB * DIN];        // 16 MB
__device__ __half g_xl[(size_t)BB * DIN];        // 16 MB
__device__ __half g_wh[(size_t)NTOT * DIN];      // 24 MB
__device__ __half g_wl[(size_t)NTOT * DIN];      // 24 MB
__device__ float  g_u [(size_t)BB * NTOT];       // 384 MB
__device__ float  g_ent[BB];

// ---------------- K0: fp32 -> (hi, lo) fp16 split ----------------
__global__ void split_kernel(const float* __restrict__ src,
                             __half* __restrict__ hi, __half* __restrict__ lo) {
    size_t i = (size_t)blockIdx.x * blockDim.x + threadIdx.x;
    float4 f = ((const float4*)src)[i];
    __half h0 = __float2half_rn(f.x), h1 = __float2half_rn(f.y);
    __half h2 = __float2half_rn(f.z), h3 = __float2half_rn(f.w);
    ((__half2*)hi)[2*i]   = __halves2half2(h0, h1);
    ((__half2*)hi)[2*i+1] = __halves2half2(h2, h3);
    ((__half2*)lo)[2*i]   = __halves2half2(__float2half_rn(f.x - __half2float(h0)),
                                           __float2half_rn(f.y - __half2float(h1)));
    ((__half2*)lo)[2*i+1] = __halves2half2(__float2half_rn(f.z - __half2float(h2)),
                                           __float2half_rn(f.w - __half2float(h3)));
}

// ---------------- K1: split-fp16 HMMA GEMM  u = x @ W^T + bias (fp32 out) ----------
#define BM 128
#define BN 256
#define BK 32
#define STAGES 3
#define NSTG (DIN / BK)        // 32
#define APITCH 80              // bytes per smem row (32 halfs data + pad)
#define A_BYTES (BM * APITCH)              // 10240
#define B_BYTES (BN * APITCH)              // 20480
#define STG_BYTES (2*A_BYTES + 2*B_BYTES)  // 61440
#define SMEM_TOTAL (STAGES * STG_BYTES)    // 184320
// stage offsets: AH 0 | AL 10240 | BH 20480 | BL 40960

__device__ __forceinline__ uint32_t smem_u32(const void* p) {
    uint32_t a;
    asm("{ .reg .u64 t; cvta.to.shared.u64 t, %1; cvt.u32.u64 %0, t; }" : "=r"(a) : "l"(p));
    return a;
}
__device__ __forceinline__ void cp_async16(uint32_t sdst, const void* gsrc) {
    asm volatile("cp.async.cg.shared.global [%0], [%1], 16;" :: "r"(sdst), "l"(gsrc) : "memory");
}
#define CP_COMMIT() asm volatile("cp.async.commit_group;" ::: "memory")
#define CP_WAIT(N)  asm volatile("cp.async.wait_group %0;" :: "n"(N) : "memory")

__device__ __forceinline__ void ldsm_x4(uint32_t addr, uint32_t& r0, uint32_t& r1,
                                        uint32_t& r2, uint32_t& r3) {
    asm volatile("ldmatrix.sync.aligned.m8n8.x4.shared.b16 {%0,%1,%2,%3}, [%4];"
                 : "=r"(r0), "=r"(r1), "=r"(r2), "=r"(r3) : "r"(addr));
}
__device__ __forceinline__ void mma16816(float* c, const uint32_t* a, const uint32_t* b) {
    asm volatile(
        "mma.sync.aligned.m16n8k16.row.col.f32.f16.f16.f32 "
        "{%0,%1,%2,%3},{%4,%5,%6,%7},{%8,%9},{%0,%1,%2,%3};"
        : "+f"(c[0]), "+f"(c[1]), "+f"(c[2]), "+f"(c[3])
        : "r"(a[0]), "r"(a[1]), "r"(a[2]), "r"(a[3]), "r"(b[0]), "r"(b[1]));
}

__global__ void __launch_bounds__(256, 1)
gemm_kernel(const float* __restrict__ bias) {
    extern __shared__ __align__(128) char smem[];
    uint32_t sb = smem_u32(smem);
    const int tid  = threadIdx.x;
    const int wid  = tid >> 5;
    const int lane = tid & 31;

    // rasterization: 32 m-tiles per group, sweep n inside the group
    const int NT = NTOT / BN;                 // 48 n-tiles
    const int GM = 32;
    int id = blockIdx.x;
    int group = id / (GM * NT), rem = id % (GM * NT);
    const int m0 = (group * GM + (rem % GM)) * BM;
    const int n0 = (rem / GM) * BN;

    // 8 warps: 2 m x 4 n, warp tile 64x64
    const int wr = wid & 1;
    const int wc = wid >> 1;

    auto load_stage = [&](int ks) {
        uint32_t st = sb + (ks % STAGES) * STG_BYTES;
        int koff = ks * BK;
#pragma unroll
        for (int i = 0; i < 2; i++) {           // A: 512 chunks of 16B, x2 terms
            int idx = i * 256 + tid, r = idx >> 2, cc = idx & 3;
            uint32_t so = (uint32_t)(r * APITCH + cc * 16);
            size_t go = (size_t)(m0 + r) * DIN + koff + cc * 8;
            cp_async16(st + so,           g_xh + go);
            cp_async16(st + A_BYTES + so, g_xl + go);
        }
#pragma unroll
        for (int i = 0; i < 4; i++) {           // B: 1024 chunks, x2 terms
            int idx = i * 256 + tid, r = idx >> 2, cc = idx & 3;
            uint32_t so = (uint32_t)(r * APITCH + cc * 16);
            size_t go = (size_t)(n0 + r) * DIN + koff + cc * 8;
            cp_async16(st + 2*A_BYTES + so,           g_wh + go);
            cp_async16(st + 2*A_BYTES + B_BYTES + so, g_wl + go);
        }
        CP_COMMIT();
    };

    float c[4][8][4];
#pragma unroll
    for (int i = 0; i < 4; i++)
#pragma unroll
        for (int j = 0; j < 8; j++)
#pragma unroll
            for (int k = 0; k < 4; k++) c[i][j][k] = 0.f;

    load_stage(0);
    load_stage(1);

    const uint32_t a_lane = (uint32_t)((lane & 15) * APITCH + (lane >> 4) * 16);
    const uint32_t b_lane = (uint32_t)(((lane & 7) + ((lane >> 4) & 1) * 8) * APITCH
                                       + ((lane >> 3) & 1) * 16);

    for (int ks = 0; ks < NSTG; ks++) {
        if (ks < NSTG - 1) { CP_WAIT(1); } else { CP_WAIT(0); }
        __syncthreads();
        if (ks + 2 < NSTG) load_stage(ks + 2);

        uint32_t st  = sb + (ks % STAGES) * STG_BYTES;
        uint32_t awh = st + wr * 64 * APITCH + a_lane;
        uint32_t awl = awh + A_BYTES;
        uint32_t bwh = st + 2*A_BYTES + wc * 64 * APITCH + b_lane;
        uint32_t bwl = bwh + B_BYTES;
#pragma unroll
        for (int kk = 0; kk < 2; kk++) {
            uint32_t koff = kk * 32;            // 16 halfs
            uint32_t ah[4][4], al[4][4];
#pragma unroll
            for (int mt = 0; mt < 4; mt++) {
                ldsm_x4(awh + mt * 16 * APITCH + koff, ah[mt][0], ah[mt][1], ah[mt][2], ah[mt][3]);
                ldsm_x4(awl + mt * 16 * APITCH + koff, al[mt][0], al[mt][1], al[mt][2], al[mt][3]);
            }
            uint32_t b[8][2];
#pragma unroll
            for (int q = 0; q < 4; q++) {       // B hi: 64 cols
                uint32_t r0, r1, r2, r3;
                ldsm_x4(bwh + q * 16 * APITCH + koff, r0, r1, r2, r3);
                b[q*2][0] = r0; b[q*2][1] = r1; b[q*2+1][0] = r2; b[q*2+1][1] = r3;
            }
#pragma unroll
            for (int mt = 0; mt < 4; mt++)
#pragma unroll
                for (int nt = 0; nt < 8; nt++) {
                    mma16816(c[mt][nt], ah[mt], b[nt]);
                    mma16816(c[mt][nt], al[mt], b[nt]);
                }
#pragma unroll
            for (int q = 0; q < 4; q++) {       // B lo
                uint32_t r0, r1, r2, r3;
                ldsm_x4(bwl + q * 16 * APITCH + koff, r0, r1, r2, r3);
                b[q*2][0] = r0; b[q*2][1] = r1; b[q*2+1][0] = r2; b[q*2+1][1] = r3;
            }
#pragma unroll
            for (int mt = 0; mt < 4; mt++)
#pragma unroll
                for (int nt = 0; nt < 8; nt++)
                    mma16816(c[mt][nt], ah[mt], b[nt]);
        }
        __syncthreads();
    }

    // epilogue: + bias, fp32 store
    const int rbase = m0 + wr * 64 + (lane >> 2);
    const int cbase = n0 + wc * 64 + (lane & 3) * 2;
#pragma unroll
    for (int nt = 0; nt < 8; nt++) {
        int col = cbase + nt * 8;
        float2 bv = *(const float2*)(bias + col);
#pragma unroll
        for (int mt = 0; mt < 4; mt++) {
            int r0 = rbase + mt * 16;
            float* p0 = g_u + (size_t)r0 * NTOT + col;
            float* p1 = g_u + (size_t)(r0 + 8) * NTOT + col;
            *(float2*)p0 = make_float2(c[mt][nt][0] + bv.x, c[mt][nt][1] + bv.y);
            *(float2*)p1 = make_float2(c[mt][nt][2] + bv.x, c[mt][nt][3] + bv.y);
        }
    }
}

// ---------------- K2: per-row routing + entropy ----------------
__device__ __forceinline__ float bsum(float v, float* s8, int wid, int lid) {
#pragma unroll
    for (int o = 16; o > 0; o >>= 1) v += __shfl_down_sync(0xffffffffu, v, o);
    __syncthreads();
    if (lid == 0) s8[wid] = v;
    __syncthreads();
    float r = 0.f;
#pragma unroll
    for (int w = 0; w < 8; w++) r += s8[w];
    return r;
}
__device__ __forceinline__ float bmax(float v, float* s8, int wid, int lid) {
#pragma unroll
    for (int o = 16; o > 0; o >>= 1) v = fmaxf(v, __shfl_down_sync(0xffffffffu, v, o));
    __syncthreads();
    if (lid == 0) s8[wid] = v;
    __syncthreads();
    float r = s8[0];
#pragma unroll
    for (int w = 1; w < 8; w++) r = fmaxf(r, s8[w]);
    return r;
}

#define RT_SMEM (NTOT*4 + 8*CCAP*4 + 8*4)   // 49568

__global__ void __launch_bounds__(256) routing_kernel(float* __restrict__ out) {
    extern __shared__ __align__(16) char rsm[];
    float* s_u   = (float*)rsm;                       // 12288 floats
    float* s_red = (float*)(rsm + NTOT * 4);          // 8*CCAP
    float* s_s8  = (float*)(rsm + NTOT * 4 + 8 * CCAP * 4);

    int b = blockIdx.x, tid = threadIdx.x;
    int wid = tid >> 5, lid = tid & 31;

    const float4* src = (const float4*)(g_u + (size_t)b * NTOT);
#pragma unroll
    for (int i = 0; i < 12; i++) ((float4*)s_u)[i * 256 + tid] = src[i * 256 + tid];
    __syncthreads();

    float u[CCAP][4];
    int j0 = tid * 4;
#pragma unroll
    for (int cc = 0; cc < CCAP; cc++) {
        float4 f = *(const float4*)(s_u + cc * DOUT + j0);
        u[cc][0] = f.x; u[cc][1] = f.y; u[cc][2] = f.z; u[cc][3] = f.w;
    }

    float blog[CCAP];
#pragma unroll
    for (int cc = 0; cc < CCAP; cc++) blog[cc] = 0.f;

    float s[4] = {0.f, 0.f, 0.f, 0.f}, scale = 0.f;
#pragma unroll 1
    for (int it = 0; it < 3; it++) {
        float mx = blog[0];
#pragma unroll
        for (int cc = 1; cc < CCAP; cc++) mx = fmaxf(mx, blog[cc]);
        float cw[CCAP], csum = 0.f;
#pragma unroll
        for (int cc = 0; cc < CCAP; cc++) { cw[cc] = expf(blog[cc] - mx); csum += cw[cc]; }
        float inv = 1.f / csum;
#pragma unroll
        for (int j = 0; j < 4; j++) {
            float a = 0.f;
#pragma unroll
            for (int cc = 0; cc < CCAP; cc++) a += cw[cc] * u[cc][j];
            s[j] = a * inv;
        }
        float n2 = bsum(s[0]*s[0] + s[1]*s[1] + s[2]*s[2] + s[3]*s[3], s_s8, wid, lid);
        float nrm = sqrtf(n2);
        scale = n2 / ((1.f + n2) * (nrm + 1e-8f));
        if (it < 2) {
            float dp[CCAP];
#pragma unroll
            for (int cc = 0; cc < CCAP; cc++) {
                float a = u[cc][0]*s[0] + u[cc][1]*s[1] + u[cc][2]*s[2] + u[cc][3]*s[3];
#pragma unroll
                for (int o = 16; o > 0; o >>= 1) a += __shfl_down_sync(0xffffffffu, a, o);
                dp[cc] = a;
            }
            __syncthreads();
            if (lid == 0)
#pragma unroll
                for (int cc = 0; cc < CCAP; cc++) s_red[wid * CCAP + cc] = dp[cc];
            __syncthreads();
#pragma unroll
            for (int cc = 0; cc < CCAP; cc++) {
                float d = 0.f;
#pragma unroll
                for (int w = 0; w < 8; w++) d += s_red[w * CCAP + cc];
                blog[cc] += scale * d;
            }
        }
    }

    // v = squash(s), replicated over AREP
    float4 v4 = make_float4(scale * s[0], scale * s[1], scale * s[2], scale * s[3]);
    size_t obase = ((size_t)b * AREP) * DOUT + j0;
#pragma unroll
    for (int a = 0; a < AREP; a++) *(float4*)(out + obase + (size_t)a * DOUT) = v4;

    // entropy over the 1024 dims of s
    float smx = bmax(fmaxf(fmaxf(s[0], s[1]), fmaxf(s[2], s[3])), s_s8, wid, lid);
    float e[4], zp = 0.f;
#pragma unroll
    for (int j = 0; j < 4; j++) { e[j] = expf(s[j] - smx); zp += e[j]; }
    float Z = bsum(zp, s_s8, wid, lid) + 1e-10f;
    float ep = 0.f;
#pragma unroll
    for (int j = 0; j < 4; j++) { float p = e[j] / Z; ep -= p * logf(p + 1e-10f); }
    float ent = bsum(ep, s_s8, wid, lid);
    if (tid == 0) g_ent[b] = fminf(fmaxf(ent, 0.f), 10.f);
}

// ---------------- K3: entropy loss scalar ----------------
__global__ void loss_kernel(float* __restrict__ dst) {
    __shared__ float s8[8];
    int tid = threadIdx.x, wid = tid >> 5, lid = tid & 31;
    float a = 0.f;
    for (int i = tid; i < BB; i += 256) a += g_ent[i];
#pragma unroll
    for (int o = 16; o > 0; o >>= 1) a += __shfl_down_sync(0xffffffffu, a, o);
    if (lid == 0) s8[wid] = a;
    __syncthreads();
    if (tid == 0) {
        float t = 0.f;
#pragma unroll
        for (int w = 0; w < 8; w++) t += s8[w];
        float mean = t / (float)BB;
        dst[0] = -(1.f / (1.f + expf(-mean))) * 0.4f;
    }
}

// ---------------- launch ----------------
extern "C" void kernel_launch(void* const* d_in, const int* in_sizes, int n_in,
                              void* d_out, int out_size) {
    const float* x    = (const float*)d_in[0];
    const float* W    = (const float*)d_in[1];
    const float* bias = (const float*)d_in[2];
    float* out = (float*)d_out;

    cudaFuncSetAttribute(gemm_kernel, cudaFuncAttributeMaxDynamicSharedMemorySize, SMEM_TOTAL);
    cudaFuncSetAttribute(routing_kernel, cudaFuncAttributeMaxDynamicSharedMemorySize, RT_SMEM);

    __half *xh, *xl, *wh, *wl;
    cudaGetSymbolAddress((void**)&xh, g_xh);
    cudaGetSymbolAddress((void**)&xl, g_xl);
    cudaGetSymbolAddress((void**)&wh, g_wh);
    cudaGetSymbolAddress((void**)&wl, g_wl);

    split_kernel<<<(BB * DIN / 4) / 256, 256>>>(x, xh, xl);
    split_kernel<<<((size_t)NTOT * DIN / 4) / 256, 256>>>(W, wh, wl);
    gemm_kernel<<<(BB / BM) * (NTOT / BN), 256, SMEM_TOTAL>>>(bias);
    routing_kernel<<<BB, 256, RT_SMEM>>>(out);
    loss_kernel<<<1, 256>>>(out + (size_t)out_size - 1);
}